// round 14
// baseline (speedup 1.0000x reference)
#include <cuda_runtime.h>
#include <cuda_fp16.h>
#include <cstdint>

// Problem constants
#define B_   2
#define S_   2048
#define D_   2048
#define H_   16
#define HD_  128
#define R_   32
#define M_TOK (B_ * S_)              // 4096 tokens
#define LORA_SCALE (1.0f / 32.0f)

// ---------------------------------------------------------------------------
// Scratch (allocation-free rule: __device__ globals)
// ---------------------------------------------------------------------------
static __device__ __align__(16) __half g_qkvh[M_TOK * 3 * D_];
static __device__ __align__(16) __half g_xh[M_TOK * D_];
static __device__ __align__(16) __half g_wqh[3 * D_ * D_];   // Wqkv + LoRA folded
static __device__ __align__(16) __half g_woh[D_ * D_];       // Wout + LoRA folded
static __device__ __align__(16) __half g_ah[M_TOK * D_];

// ---------------------------------------------------------------------------
// helpers
// ---------------------------------------------------------------------------
__device__ __forceinline__ uint32_t smem_u32(const void* p) {
    uint32_t a;
    asm("{ .reg .u64 t; cvta.to.shared.u64 t, %1; cvt.u32.u64 %0, t; }"
        : "=r"(a) : "l"(p));
    return a;
}
__device__ __forceinline__ void cp16(uint32_t dst, const void* src) {
    asm volatile("cp.async.cg.shared.global [%0], [%1], 16;"
                 :: "r"(dst), "l"(src) : "memory");
}
__device__ __forceinline__ void cp_commit() {
    asm volatile("cp.async.commit_group;" ::: "memory");
}
__device__ __forceinline__ void cp_wait1() {
    asm volatile("cp.async.wait_group 1;" ::: "memory");
}
__device__ __forceinline__ void cp_wait2() {
    asm volatile("cp.async.wait_group 2;" ::: "memory");
}
__device__ __forceinline__ void ldm4(uint32_t& r0, uint32_t& r1,
                                     uint32_t& r2, uint32_t& r3, uint32_t addr) {
    asm volatile("ldmatrix.sync.aligned.m8n8.x4.shared.b16 {%0,%1,%2,%3}, [%4];"
                 : "=r"(r0), "=r"(r1), "=r"(r2), "=r"(r3) : "r"(addr));
}
__device__ __forceinline__ void ldm4t(uint32_t& r0, uint32_t& r1,
                                      uint32_t& r2, uint32_t& r3, uint32_t addr) {
    asm volatile("ldmatrix.sync.aligned.m8n8.x4.trans.shared.b16 {%0,%1,%2,%3}, [%4];"
                 : "=r"(r0), "=r"(r1), "=r"(r2), "=r"(r3) : "r"(addr));
}
__device__ __forceinline__ void mma16h(float* c, const uint32_t* a, const uint32_t* b) {
    asm volatile(
        "mma.sync.aligned.m16n8k16.row.col.f32.f16.f16.f32 "
        "{%0,%1,%2,%3}, {%4,%5,%6,%7}, {%8,%9}, {%0,%1,%2,%3};"
        : "+f"(c[0]), "+f"(c[1]), "+f"(c[2]), "+f"(c[3])
        : "r"(a[0]), "r"(a[1]), "r"(a[2]), "r"(a[3]), "r"(b[0]), "r"(b[1]));
}
__device__ __forceinline__ uint32_t packh_rn(float x, float y) {
    __half2 t = __floats2half2_rn(x, y);
    return *(uint32_t*)&t;
}

// ---------------------------------------------------------------------------
// Pre-pass: fp32 -> fp16 RN (x only)
// ---------------------------------------------------------------------------
__global__ void __launch_bounds__(256) convh_kernel(
    const float4* __restrict__ src, uint2* __restrict__ dst, int n4)
{
    int i = blockIdx.x * 256 + threadIdx.x;
    if (i >= n4) return;
    float4 v = src[i];
    dst[i] = make_uint2(packh_rn(v.x, v.y), packh_rn(v.z, v.w));
}

// ---------------------------------------------------------------------------
// Pre-pass: fold LoRA into weight, fp32 -> fp16:
//   Weff[n][k] = W[n][k] + scale * sum_r A[k][r] * Bm[r][n]
// ---------------------------------------------------------------------------
__global__ void __launch_bounds__(256) weff_kernel(
    const float* __restrict__ W, const float* __restrict__ A,
    const float* __restrict__ Bm, __half* __restrict__ outW,
    int N, int K, float scale)
{
    __shared__ float As[64][33];   // [k][r]
    __shared__ float Bs[64][33];   // [n][r]

    const int tid = threadIdx.x;
    const int k0 = blockIdx.x * 64;
    const int n0 = blockIdx.y * 64;

    #pragma unroll
    for (int j = 0; j < 8; j++) {
        int idx = tid + j * 256;
        int kk = idx >> 5, r = idx & 31;
        As[kk][r] = A[(size_t)(k0 + kk) * 32 + r];
    }
    #pragma unroll
    for (int j = 0; j < 8; j++) {
        int idx = tid + j * 256;
        int r = idx >> 6, nn = idx & 63;
        Bs[nn][r] = Bm[(size_t)r * N + n0 + nn];
    }
    __syncthreads();

    const int tk = tid & 15;
    const int tn = tid >> 4;

    float acc[4][4];
    #pragma unroll
    for (int i = 0; i < 4; i++)
        #pragma unroll
        for (int j = 0; j < 4; j++) acc[i][j] = 0.f;

    #pragma unroll
    for (int r = 0; r < 32; r++) {
        float a[4], b[4];
        #pragma unroll
        for (int j = 0; j < 4; j++) a[j] = As[tk * 4 + j][r];
        #pragma unroll
        for (int i = 0; i < 4; i++) b[i] = Bs[tn * 4 + i][r];
        #pragma unroll
        for (int i = 0; i < 4; i++)
            #pragma unroll
            for (int j = 0; j < 4; j++)
                acc[i][j] = fmaf(b[i], a[j], acc[i][j]);
    }

    #pragma unroll
    for (int i = 0; i < 4; i++) {
        int n = n0 + tn * 4 + i;
        float4 w = *(const float4*)&W[(size_t)n * K + k0 + tk * 4];
        uint2 o;
        o.x = packh_rn(fmaf(scale, acc[i][0], w.x), fmaf(scale, acc[i][1], w.y));
        o.y = packh_rn(fmaf(scale, acc[i][2], w.z), fmaf(scale, acc[i][3], w.w));
        *(uint2*)&outW[(size_t)n * K + k0 + tk * 4] = o;
    }
}

// ---------------------------------------------------------------------------
// fp16 GEMM v2 (1-pass, LoRA pre-folded into B):  C = Ah @ Bh^T
// CTA tile 256x128, 8 warps in 4x2, warp tile 64x64 (4 m-tiles x 8 n8-tiles).
// K-chunk 32, row stride 80B (conflict-free ldmatrix), 4-stage cp.async.
// outMode: 0 = fp32 Cf, 1 = fp16 (RN) Chi
// ---------------------------------------------------------------------------
#define GROW 80
#define OFF_B  (256 * GROW)               // 20480
#define STAGE_B (256 * GROW + 128 * GROW) // 30720
#define TCG_SMEM (4 * STAGE_B)            // 122880 bytes

__global__ void __launch_bounds__(256, 1) tc_gemm_fp16(
    const __half* __restrict__ Ah, const __half* __restrict__ Bh,
    float* __restrict__ Cf, uint16_t* __restrict__ Chi,
    int M, int N, int K, int outMode)
{
    extern __shared__ __align__(128) char smem[];
    const uint32_t sbase = smem_u32(smem);

    const int tid  = threadIdx.x;
    const int wid  = tid >> 5;
    const int lane = tid & 31;
    const int g    = lane >> 2;
    const int q    = lane & 3;
    const int warpM = (wid & 3) * 64;     // 4 along M
    const int warpN = (wid >> 2) * 64;    // 2 along N

    const int n0 = blockIdx.x * 128;
    const int m0 = blockIdx.y * 256;

    const int kc = K >> 5;                // chunks of 32

    float acc[4][8][4];
    #pragma unroll
    for (int i = 0; i < 4; i++)
        #pragma unroll
        for (int j = 0; j < 8; j++)
            #pragma unroll
            for (int e = 0; e < 4; e++) acc[i][j][e] = 0.f;

    auto issue = [&](int c, int s) {
        const uint32_t st = sbase + (uint32_t)s * STAGE_B;
        // A: 256 rows x 4 segs = 1024 cp16
        #pragma unroll
        for (int j = 0; j < 4; j++) {
            int idx = tid + j * 256;
            int row = idx >> 2;
            int seg = idx & 3;
            cp16(st + (uint32_t)row * GROW + (uint32_t)seg * 16u,
                 Ah + (size_t)(m0 + row) * K + c * 32 + seg * 8);
        }
        // B: 128 rows x 4 segs = 512 cp16
        #pragma unroll
        for (int j = 0; j < 2; j++) {
            int idx = tid + j * 256;
            int row = idx >> 2;
            int seg = idx & 3;
            cp16(st + OFF_B + (uint32_t)row * GROW + (uint32_t)seg * 16u,
                 Bh + (size_t)(n0 + row) * K + c * 32 + seg * 8);
        }
        cp_commit();
    };

    issue(0, 0);
    issue(1, 1);
    issue(2, 2);

    const int mi = lane >> 3;
    const int l7 = lane & 7;

    for (int i = 0; i < kc; i++) {
        cp_wait2();
        __syncthreads();
        if (i + 3 < kc) issue(i + 3, (i + 3) & 3);
        else cp_commit();

        const uint32_t st = sbase + (uint32_t)(i & 3) * STAGE_B;

        #pragma unroll
        for (int kh = 0; kh < 2; kh++) {
            uint32_t bh[8][2];
            #pragma unroll
            for (int bg = 0; bg < 4; bg++) {
                uint32_t rowB = warpN + bg * 16 + ((mi >> 1) << 3) + l7;
                uint32_t addr = st + OFF_B + rowB * GROW
                              + (uint32_t)(mi & 1) * 16u + kh * 32u;
                ldm4(bh[2 * bg][0], bh[2 * bg][1],
                     bh[2 * bg + 1][0], bh[2 * bg + 1][1], addr);
            }
            #pragma unroll
            for (int mt = 0; mt < 4; mt++) {
                uint32_t rowA = warpM + mt * 16 + ((mi & 1) << 3) + l7;
                uint32_t addrA = st + rowA * GROW
                               + (uint32_t)(mi >> 1) * 16u + kh * 32u;
                uint32_t ah[4];
                ldm4(ah[0], ah[1], ah[2], ah[3], addrA);
                #pragma unroll
                for (int nt = 0; nt < 8; nt++)
                    mma16h(acc[mt][nt], ah, bh[nt]);
            }
        }
    }

    // epilogue
    #pragma unroll
    for (int mt = 0; mt < 4; mt++) {
        int row = m0 + warpM + mt * 16 + g;
        #pragma unroll
        for (int nt = 0; nt < 8; nt++) {
            int col = n0 + warpN + nt * 8 + 2 * q;
            size_t i0 = (size_t)row * N + col;
            size_t i1 = (size_t)(row + 8) * N + col;
            if (outMode == 0) {
                *(float2*)&Cf[i0] = make_float2(acc[mt][nt][0], acc[mt][nt][1]);
                *(float2*)&Cf[i1] = make_float2(acc[mt][nt][2], acc[mt][nt][3]);
            } else {
                *(uint32_t*)&Chi[i0] = packh_rn(acc[mt][nt][0], acc[mt][nt][1]);
                *(uint32_t*)&Chi[i1] = packh_rn(acc[mt][nt][2], acc[mt][nt][3]);
            }
        }
    }
}

// ---------------------------------------------------------------------------
// Tensor-core flash attention, fp16 1-pass, occupancy-2, register-pipelined
// (unchanged from round 13 — passing)
// ---------------------------------------------------------------------------
#define AROWB 272
#define PAD_OFF 0
#define PAD_B   (S_ * 4)                       // 8192
#define QH_OFF  PAD_B
#define KV_OFF  (QH_OFF + 64 * AROWB)
#define KHO 0
#define VHO (64 * AROWB)
#define ST_B (2 * 64 * AROWB)
#define ATTN_SMEM (KV_OFF + 2 * ST_B)          // 95232

__global__ void __launch_bounds__(128, 2) attn_mma(
    const __half* __restrict__ qkvh,
    const float* __restrict__ alibi, const float* __restrict__ pad,
    uint16_t* __restrict__ outh)
{
    extern __shared__ __align__(128) char smem[];
    const uint32_t sb = smem_u32(smem);
    const int tid = threadIdx.x, wid = tid >> 5, lane = tid & 31;
    const int g = lane >> 2, q = lane & 3, l7 = lane & 7;
    const int q0 = blockIdx.x * 64, h = blockIdx.y, b = blockIdx.z;

    const size_t tokbase = (size_t)(b * S_);

    {
        const float* prow = pad + (size_t)b * S_;
        #pragma unroll
        for (int j = 0; j < 4; j++) {
            int idx = tid + j * 128;
            cp16(sb + PAD_OFF + idx * 16, prow + idx * 4);
        }
        const __half* bH = qkvh + (tokbase + q0) * 6144 + h * 128;
        #pragma unroll
        for (int j = 0; j < 8; j++) {
            int idx = tid + j * 128;
            int row = idx >> 4, seg = idx & 15;
            cp16(sb + QH_OFF + (uint32_t)row * AROWB + seg * 16,
                 bH + (size_t)row * 6144 + seg * 8);
        }
    }
    auto loadKV = [&](int kt, int st) {
        const uint32_t base = sb + KV_OFF + (uint32_t)st * ST_B;
        const __half* kH = qkvh + (tokbase + kt * 64) * 6144 + D_ + h * 128;
        const __half* vH = kH + D_;
        #pragma unroll
        for (int j = 0; j < 8; j++) {
            int idx = tid + j * 128;
            int row = idx >> 4, seg = idx & 15;
            uint32_t off = (uint32_t)row * AROWB + seg * 16;
            size_t go = (size_t)row * 6144 + seg * 8;
            cp16(base + KHO + off, kH + go);
            cp16(base + VHO + off, vH + go);
        }
    };
    cp_commit();
    loadKV(0, 0); cp_commit();
    loadKV(1, 1); cp_commit();

    float o[16][4];
    #pragma unroll
    for (int i = 0; i < 16; i++)
        #pragma unroll
        for (int e = 0; e < 4; e++) o[i][e] = 0.f;
    float m0r = -1e30f, m1r = -1e30f, l0r = 0.f, l1r = 0.f;

    const float sscale = 0.08838834764831845f;   // 1/sqrt(128)

    const uint32_t qoff = (uint32_t)(wid * 16 + ((lane >> 3) & 1) * 8 + l7) * AROWB
                        + ((lane >> 4) & 1) * 16 + QH_OFF;
    const uint32_t koff = (uint32_t)(((lane >> 4) & 1) * 8 + l7) * AROWB
                        + ((lane >> 3) & 1) * 16;
    const uint32_t voff = (uint32_t)(((lane >> 3) & 1) * 8 + l7) * AROWB
                        + ((lane >> 4) & 1) * 16;

    const float* arow0 = alibi + ((size_t)h * S_ + (q0 + wid * 16 + g)) * S_;
    const float* arow1 = arow0 + 8 * S_;
    const float* padS  = (const float*)smem;

    cp_wait1();
    __syncthreads();
    uint32_t qf[8][4];
    #pragma unroll
    for (int kc2 = 0; kc2 < 8; kc2++)
        ldm4(qf[kc2][0], qf[kc2][1], qf[kc2][2], qf[kc2][3],
             sb + qoff + kc2 * 32);

    for (int kt = 0; kt < S_ / 64; kt++) {
        cp_wait1();
        __syncthreads();
        const uint32_t st = sb + KV_OFF + (uint32_t)(kt & 1) * ST_B;
        const int k0 = kt * 64;

        float c[8][4];
        #pragma unroll
        for (int i = 0; i < 8; i++)
            #pragma unroll
            for (int e = 0; e < 4; e++) c[i][e] = 0.f;

        uint32_t kf[2][4][4];
        #pragma unroll
        for (int np = 0; np < 4; np++)
            ldm4(kf[0][np][0], kf[0][np][1], kf[0][np][2], kf[0][np][3],
                 st + KHO + koff + (uint32_t)np * (16 * AROWB));

        #pragma unroll
        for (int kc2 = 0; kc2 < 8; kc2++) {
            const int cur = kc2 & 1, nxt = cur ^ 1;
            if (kc2 < 7) {
                #pragma unroll
                for (int np = 0; np < 4; np++)
                    ldm4(kf[nxt][np][0], kf[nxt][np][1],
                         kf[nxt][np][2], kf[nxt][np][3],
                         st + KHO + koff + (uint32_t)np * (16 * AROWB)
                            + (kc2 + 1) * 32);
            }
            #pragma unroll
            for (int np = 0; np < 4; np++) {
                mma16h(c[2 * np],     qf[kc2], &kf[cur][np][0]);
                mma16h(c[2 * np + 1], qf[kc2], &kf[cur][np][2]);
            }
        }

        #pragma unroll
        for (int nt = 0; nt < 8; nt++) {
            int col = k0 + nt * 8 + 2 * q;
            float2 a0 = *(const float2*)(arow0 + col);
            float2 a1 = *(const float2*)(arow1 + col);
            float2 pd = *(const float2*)(padS + col);
            c[nt][0] = fmaf(c[nt][0], sscale, a0.x + pd.x);
            c[nt][1] = fmaf(c[nt][1], sscale, a0.y + pd.y);
            c[nt][2] = fmaf(c[nt][2], sscale, a1.x + pd.x);
            c[nt][3] = fmaf(c[nt][3], sscale, a1.y + pd.y);
        }
        float mx0 = -1e30f, mx1 = -1e30f;
        #pragma unroll
        for (int nt = 0; nt < 8; nt++) {
            mx0 = fmaxf(mx0, fmaxf(c[nt][0], c[nt][1]));
            mx1 = fmaxf(mx1, fmaxf(c[nt][2], c[nt][3]));
        }
        mx0 = fmaxf(mx0, __shfl_xor_sync(0xffffffffu, mx0, 1));
        mx0 = fmaxf(mx0, __shfl_xor_sync(0xffffffffu, mx0, 2));
        mx1 = fmaxf(mx1, __shfl_xor_sync(0xffffffffu, mx1, 1));
        mx1 = fmaxf(mx1, __shfl_xor_sync(0xffffffffu, mx1, 2));
        float mn0 = fmaxf(m0r, mx0), mn1 = fmaxf(m1r, mx1);
        float cr0 = __expf(m0r - mn0), cr1 = __expf(m1r - mn1);
        m0r = mn0; m1r = mn1;
        float s0 = 0.f, s1 = 0.f;
        #pragma unroll
        for (int nt = 0; nt < 8; nt++) {
            c[nt][0] = __expf(c[nt][0] - mn0);
            c[nt][1] = __expf(c[nt][1] - mn0);
            c[nt][2] = __expf(c[nt][2] - mn1);
            c[nt][3] = __expf(c[nt][3] - mn1);
            s0 += c[nt][0] + c[nt][1];
            s1 += c[nt][2] + c[nt][3];
        }
        s0 += __shfl_xor_sync(0xffffffffu, s0, 1);
        s0 += __shfl_xor_sync(0xffffffffu, s0, 2);
        s1 += __shfl_xor_sync(0xffffffffu, s1, 1);
        s1 += __shfl_xor_sync(0xffffffffu, s1, 2);
        l0r = l0r * cr0 + s0;
        l1r = l1r * cr1 + s1;
        #pragma unroll
        for (int i = 0; i < 16; i++) {
            o[i][0] *= cr0; o[i][1] *= cr0;
            o[i][2] *= cr1; o[i][3] *= cr1;
        }

        #pragma unroll
        for (int kc2 = 0; kc2 < 4; kc2++) {
            uint32_t ph[4];
            ph[0] = packh_rn(c[2 * kc2][0],     c[2 * kc2][1]);
            ph[1] = packh_rn(c[2 * kc2][2],     c[2 * kc2][3]);
            ph[2] = packh_rn(c[2 * kc2 + 1][0], c[2 * kc2 + 1][1]);
            ph[3] = packh_rn(c[2 * kc2 + 1][2], c[2 * kc2 + 1][3]);
            uint32_t vrow = st + VHO + voff + (uint32_t)kc2 * (16 * AROWB);
            uint32_t vf[2][4];
            ldm4t(vf[0][0], vf[0][1], vf[0][2], vf[0][3], vrow);
            #pragma unroll
            for (int dg = 0; dg < 8; dg++) {
                const int cur = dg & 1, nxt = cur ^ 1;
                if (dg < 7)
                    ldm4t(vf[nxt][0], vf[nxt][1], vf[nxt][2], vf[nxt][3],
                          vrow + (dg + 1) * 32);
                mma16h(o[2 * dg],     ph, &vf[cur][0]);
                mma16h(o[2 * dg + 1], ph, &vf[cur][2]);
            }
        }

        __syncthreads();
        if (kt + 2 < S_ / 64) { loadKV(kt + 2, kt & 1); cp_commit(); }
        else cp_commit();
    }

    float inv0 = 1.0f / l0r, inv1 = 1.0f / l1r;
    size_t row0 = tokbase + q0 + wid * 16 + g;
    size_t row1 = row0 + 8;
    #pragma unroll
    for (int nt = 0; nt < 16; nt++) {
        int col = h * 128 + nt * 8 + 2 * q;
        *(uint32_t*)&outh[row0 * D_ + col] =
            packh_rn(o[nt][0] * inv0, o[nt][1] * inv0);
        *(uint32_t*)&outh[row1 * D_ + col] =
            packh_rn(o[nt][2] * inv1, o[nt][3] * inv1);
    }
}

// ---------------------------------------------------------------------------
// kernel_launch
// ---------------------------------------------------------------------------
extern "C" void kernel_launch(void* const* d_in, const int* in_sizes, int n_in,
                              void* d_out, int out_size)
{
    const float* x     = (const float*)d_in[0];
    const float* alibi = (const float*)d_in[1];
    const float* pad   = (const float*)d_in[2];
    const float* Wqkv  = (const float*)d_in[3];
    const float* Aqkv  = (const float*)d_in[4];
    const float* Bqkv  = (const float*)d_in[5];
    const float* Wout  = (const float*)d_in[6];
    const float* Aout  = (const float*)d_in[7];
    const float* Bout  = (const float*)d_in[8];
    float* out = (float*)d_out;

    __half *qkvh, *xh, *wqh, *woh, *ah;
    cudaGetSymbolAddress((void**)&qkvh, g_qkvh);
    cudaGetSymbolAddress((void**)&xh,  g_xh);
    cudaGetSymbolAddress((void**)&wqh, g_wqh);
    cudaGetSymbolAddress((void**)&woh, g_woh);
    cudaGetSymbolAddress((void**)&ah,  g_ah);

    cudaFuncSetAttribute(tc_gemm_fp16,
                         cudaFuncAttributeMaxDynamicSharedMemorySize, TCG_SMEM);
    cudaFuncSetAttribute(attn_mma,
                         cudaFuncAttributeMaxDynamicSharedMemorySize, ATTN_SMEM);

    // pre-pass: x -> fp16; weights -> fp16 with LoRA folded in fp32
    convh_kernel<<<(M_TOK * D_ / 4 + 255) / 256, 256>>>(
        (const float4*)x, (uint2*)xh, M_TOK * D_ / 4);
    {
        dim3 gq(D_ / 64, (3 * D_) / 64);
        weff_kernel<<<gq, 256>>>(Wqkv, Aqkv, Bqkv, wqh, 3 * D_, D_, LORA_SCALE);
        dim3 go(D_ / 64, D_ / 64);
        weff_kernel<<<go, 256>>>(Wout, Aout, Bout, woh, D_, D_, LORA_SCALE);
    }

    // qkv = x @ Weff_qkv^T  -> fp16 (1-pass)
    {
        dim3 grid((3 * D_) / 128, M_TOK / 256);
        tc_gemm_fp16<<<grid, 256, TCG_SMEM>>>(xh, wqh,
                                              nullptr, (uint16_t*)qkvh,
                                              M_TOK, 3 * D_, D_, 1);
    }

    // attention -> fp16 ah
    {
        dim3 grid(S_ / 64, H_, B_);
        attn_mma<<<grid, 128, ATTN_SMEM>>>(qkvh, alibi, pad, (uint16_t*)ah);
    }

    // out = attn @ Weff_out^T  -> fp32 (1-pass)
    {
        dim3 grid(D_ / 128, M_TOK / 256);
        tc_gemm_fp16<<<grid, 256, TCG_SMEM>>>(ah, woh,
                                              out, nullptr,
                                              M_TOK, D_, D_, 0);
    }
}

// round 15
// speedup vs baseline: 1.1635x; 1.1635x over previous
#include <cuda_runtime.h>
#include <cuda_fp16.h>
#include <cstdint>

// Problem constants
#define B_   2
#define S_   2048
#define D_   2048
#define H_   16
#define HD_  128
#define R_   32
#define M_TOK (B_ * S_)              // 4096 tokens
#define LORA_SCALE (1.0f / 32.0f)

// ---------------------------------------------------------------------------
// Scratch (allocation-free rule: __device__ globals)
// ---------------------------------------------------------------------------
static __device__ __align__(16) __half g_qkvh[M_TOK * 3 * D_];
static __device__ __align__(16) __half g_xh[M_TOK * D_];
static __device__ __align__(16) __half g_wqh[3 * D_ * D_];   // Wqkv + LoRA folded
static __device__ __align__(16) __half g_woh[D_ * D_];       // Wout + LoRA folded
static __device__ __align__(16) __half g_ah[M_TOK * D_];

// ---------------------------------------------------------------------------
// helpers
// ---------------------------------------------------------------------------
__device__ __forceinline__ uint32_t smem_u32(const void* p) {
    uint32_t a;
    asm("{ .reg .u64 t; cvta.to.shared.u64 t, %1; cvt.u32.u64 %0, t; }"
        : "=r"(a) : "l"(p));
    return a;
}
__device__ __forceinline__ void cp16(uint32_t dst, const void* src) {
    asm volatile("cp.async.cg.shared.global [%0], [%1], 16;"
                 :: "r"(dst), "l"(src) : "memory");
}
__device__ __forceinline__ void cp_commit() {
    asm volatile("cp.async.commit_group;" ::: "memory");
}
__device__ __forceinline__ void cp_wait1() {
    asm volatile("cp.async.wait_group 1;" ::: "memory");
}
__device__ __forceinline__ void cp_wait2() {
    asm volatile("cp.async.wait_group 2;" ::: "memory");
}
__device__ __forceinline__ void ldm4(uint32_t& r0, uint32_t& r1,
                                     uint32_t& r2, uint32_t& r3, uint32_t addr) {
    asm volatile("ldmatrix.sync.aligned.m8n8.x4.shared.b16 {%0,%1,%2,%3}, [%4];"
                 : "=r"(r0), "=r"(r1), "=r"(r2), "=r"(r3) : "r"(addr));
}
__device__ __forceinline__ void ldm4t(uint32_t& r0, uint32_t& r1,
                                      uint32_t& r2, uint32_t& r3, uint32_t addr) {
    asm volatile("ldmatrix.sync.aligned.m8n8.x4.trans.shared.b16 {%0,%1,%2,%3}, [%4];"
                 : "=r"(r0), "=r"(r1), "=r"(r2), "=r"(r3) : "r"(addr));
}
__device__ __forceinline__ void mma16h(float* c, const uint32_t* a, const uint32_t* b) {
    asm volatile(
        "mma.sync.aligned.m16n8k16.row.col.f32.f16.f16.f32 "
        "{%0,%1,%2,%3}, {%4,%5,%6,%7}, {%8,%9}, {%0,%1,%2,%3};"
        : "+f"(c[0]), "+f"(c[1]), "+f"(c[2]), "+f"(c[3])
        : "r"(a[0]), "r"(a[1]), "r"(a[2]), "r"(a[3]), "r"(b[0]), "r"(b[1]));
}
__device__ __forceinline__ uint32_t packh_rn(float x, float y) {
    __half2 t = __floats2half2_rn(x, y);
    return *(uint32_t*)&t;
}

// ---------------------------------------------------------------------------
// Pre-pass: fp32 -> fp16 RN (x only)
// ---------------------------------------------------------------------------
__global__ void __launch_bounds__(256) convh_kernel(
    const float4* __restrict__ src, uint2* __restrict__ dst, int n4)
{
    int i = blockIdx.x * 256 + threadIdx.x;
    if (i >= n4) return;
    float4 v = src[i];
    dst[i] = make_uint2(packh_rn(v.x, v.y), packh_rn(v.z, v.w));
}

// ---------------------------------------------------------------------------
// Pre-pass: fold LoRA into weight, fp32 -> fp16:
//   Weff[n][k] = W[n][k] + scale * sum_r A[k][r] * Bm[r][n]
// ---------------------------------------------------------------------------
__global__ void __launch_bounds__(256) weff_kernel(
    const float* __restrict__ W, const float* __restrict__ A,
    const float* __restrict__ Bm, __half* __restrict__ outW,
    int N, int K, float scale)
{
    __shared__ float As[64][33];   // [k][r]
    __shared__ float Bs[64][33];   // [n][r]

    const int tid = threadIdx.x;
    const int k0 = blockIdx.x * 64;
    const int n0 = blockIdx.y * 64;

    #pragma unroll
    for (int j = 0; j < 8; j++) {
        int idx = tid + j * 256;
        int kk = idx >> 5, r = idx & 31;
        As[kk][r] = A[(size_t)(k0 + kk) * 32 + r];
    }
    #pragma unroll
    for (int j = 0; j < 8; j++) {
        int idx = tid + j * 256;
        int r = idx >> 6, nn = idx & 63;
        Bs[nn][r] = Bm[(size_t)r * N + n0 + nn];
    }
    __syncthreads();

    const int tk = tid & 15;
    const int tn = tid >> 4;

    float acc[4][4];
    #pragma unroll
    for (int i = 0; i < 4; i++)
        #pragma unroll
        for (int j = 0; j < 4; j++) acc[i][j] = 0.f;

    #pragma unroll
    for (int r = 0; r < 32; r++) {
        float a[4], b[4];
        #pragma unroll
        for (int j = 0; j < 4; j++) a[j] = As[tk * 4 + j][r];
        #pragma unroll
        for (int i = 0; i < 4; i++) b[i] = Bs[tn * 4 + i][r];
        #pragma unroll
        for (int i = 0; i < 4; i++)
            #pragma unroll
            for (int j = 0; j < 4; j++)
                acc[i][j] = fmaf(b[i], a[j], acc[i][j]);
    }

    #pragma unroll
    for (int i = 0; i < 4; i++) {
        int n = n0 + tn * 4 + i;
        float4 w = *(const float4*)&W[(size_t)n * K + k0 + tk * 4];
        uint2 o;
        o.x = packh_rn(fmaf(scale, acc[i][0], w.x), fmaf(scale, acc[i][1], w.y));
        o.y = packh_rn(fmaf(scale, acc[i][2], w.z), fmaf(scale, acc[i][3], w.w));
        *(uint2*)&outW[(size_t)n * K + k0 + tk * 4] = o;
    }
}

// ---------------------------------------------------------------------------
// fp16 GEMM v3 (1-pass, LoRA pre-folded into B):  C = Ah @ Bh^T
// CTA tile 128x128, 4 warps in 2x2, warp tile 64x64 -> occ 2.
// K-chunk 32, row stride 80B (conflict-free ldmatrix), 4-stage cp.async.
// outMode: 0 = fp32 Cf, 1 = fp16 (RN) Chi
// ---------------------------------------------------------------------------
#define GROW 80
#define OFF_B  (128 * GROW)               // 10240
#define STAGE_B (2 * 128 * GROW)          // 20480
#define TCG_SMEM (4 * STAGE_B)            // 81920 bytes

__global__ void __launch_bounds__(128, 2) tc_gemm_fp16(
    const __half* __restrict__ Ah, const __half* __restrict__ Bh,
    float* __restrict__ Cf, uint16_t* __restrict__ Chi,
    int M, int N, int K, int outMode)
{
    extern __shared__ __align__(128) char smem[];
    const uint32_t sbase = smem_u32(smem);

    const int tid  = threadIdx.x;
    const int wid  = tid >> 5;
    const int lane = tid & 31;
    const int g    = lane >> 2;
    const int q    = lane & 3;
    const int warpM = (wid & 1) * 64;     // 2 along M
    const int warpN = (wid >> 1) * 64;    // 2 along N

    const int n0 = blockIdx.x * 128;
    const int m0 = blockIdx.y * 128;

    const int kc = K >> 5;                // chunks of 32

    float acc[4][8][4];
    #pragma unroll
    for (int i = 0; i < 4; i++)
        #pragma unroll
        for (int j = 0; j < 8; j++)
            #pragma unroll
            for (int e = 0; e < 4; e++) acc[i][j][e] = 0.f;

    auto issue = [&](int c, int s) {
        const uint32_t st = sbase + (uint32_t)s * STAGE_B;
        // A: 128 rows x 4 segs = 512 cp16; B same -> 8 cp16/thread
        #pragma unroll
        for (int j = 0; j < 4; j++) {
            int idx = tid + j * 128;
            int row = idx >> 2;
            int seg = idx & 3;
            uint32_t doff = (uint32_t)row * GROW + (uint32_t)seg * 16u;
            cp16(st + doff,         Ah + (size_t)(m0 + row) * K + c * 32 + seg * 8);
            cp16(st + OFF_B + doff, Bh + (size_t)(n0 + row) * K + c * 32 + seg * 8);
        }
        cp_commit();
    };

    issue(0, 0);
    issue(1, 1);
    issue(2, 2);

    const int mi = lane >> 3;
    const int l7 = lane & 7;

    for (int i = 0; i < kc; i++) {
        cp_wait2();
        __syncthreads();
        if (i + 3 < kc) issue(i + 3, (i + 3) & 3);
        else cp_commit();

        const uint32_t st = sbase + (uint32_t)(i & 3) * STAGE_B;

        #pragma unroll
        for (int kh = 0; kh < 2; kh++) {
            uint32_t bh[8][2];
            #pragma unroll
            for (int bg = 0; bg < 4; bg++) {
                uint32_t rowB = warpN + bg * 16 + ((mi >> 1) << 3) + l7;
                uint32_t addr = st + OFF_B + rowB * GROW
                              + (uint32_t)(mi & 1) * 16u + kh * 32u;
                ldm4(bh[2 * bg][0], bh[2 * bg][1],
                     bh[2 * bg + 1][0], bh[2 * bg + 1][1], addr);
            }
            #pragma unroll
            for (int mt = 0; mt < 4; mt++) {
                uint32_t rowA = warpM + mt * 16 + ((mi & 1) << 3) + l7;
                uint32_t addrA = st + rowA * GROW
                               + (uint32_t)(mi >> 1) * 16u + kh * 32u;
                uint32_t ah[4];
                ldm4(ah[0], ah[1], ah[2], ah[3], addrA);
                #pragma unroll
                for (int nt = 0; nt < 8; nt++)
                    mma16h(acc[mt][nt], ah, bh[nt]);
            }
        }
    }

    // epilogue
    #pragma unroll
    for (int mt = 0; mt < 4; mt++) {
        int row = m0 + warpM + mt * 16 + g;
        #pragma unroll
        for (int nt = 0; nt < 8; nt++) {
            int col = n0 + warpN + nt * 8 + 2 * q;
            size_t i0 = (size_t)row * N + col;
            size_t i1 = (size_t)(row + 8) * N + col;
            if (outMode == 0) {
                *(float2*)&Cf[i0] = make_float2(acc[mt][nt][0], acc[mt][nt][1]);
                *(float2*)&Cf[i1] = make_float2(acc[mt][nt][2], acc[mt][nt][3]);
            } else {
                *(uint32_t*)&Chi[i0] = packh_rn(acc[mt][nt][0], acc[mt][nt][1]);
                *(uint32_t*)&Chi[i1] = packh_rn(acc[mt][nt][2], acc[mt][nt][3]);
            }
        }
    }
}

// ---------------------------------------------------------------------------
// Tensor-core flash attention, fp16 1-pass, occupancy-2, register-pipelined
// (unchanged from round 13 — passing)
// ---------------------------------------------------------------------------
#define AROWB 272
#define PAD_OFF 0
#define PAD_B   (S_ * 4)                       // 8192
#define QH_OFF  PAD_B
#define KV_OFF  (QH_OFF + 64 * AROWB)
#define KHO 0
#define VHO (64 * AROWB)
#define ST_B (2 * 64 * AROWB)
#define ATTN_SMEM (KV_OFF + 2 * ST_B)          // 95232

__global__ void __launch_bounds__(128, 2) attn_mma(
    const __half* __restrict__ qkvh,
    const float* __restrict__ alibi, const float* __restrict__ pad,
    uint16_t* __restrict__ outh)
{
    extern __shared__ __align__(128) char smem[];
    const uint32_t sb = smem_u32(smem);
    const int tid = threadIdx.x, wid = tid >> 5, lane = tid & 31;
    const int g = lane >> 2, q = lane & 3, l7 = lane & 7;
    const int q0 = blockIdx.x * 64, h = blockIdx.y, b = blockIdx.z;

    const size_t tokbase = (size_t)(b * S_);

    {
        const float* prow = pad + (size_t)b * S_;
        #pragma unroll
        for (int j = 0; j < 4; j++) {
            int idx = tid + j * 128;
            cp16(sb + PAD_OFF + idx * 16, prow + idx * 4);
        }
        const __half* bH = qkvh + (tokbase + q0) * 6144 + h * 128;
        #pragma unroll
        for (int j = 0; j < 8; j++) {
            int idx = tid + j * 128;
            int row = idx >> 4, seg = idx & 15;
            cp16(sb + QH_OFF + (uint32_t)row * AROWB + seg * 16,
                 bH + (size_t)row * 6144 + seg * 8);
        }
    }
    auto loadKV = [&](int kt, int st) {
        const uint32_t base = sb + KV_OFF + (uint32_t)st * ST_B;
        const __half* kH = qkvh + (tokbase + kt * 64) * 6144 + D_ + h * 128;
        const __half* vH = kH + D_;
        #pragma unroll
        for (int j = 0; j < 8; j++) {
            int idx = tid + j * 128;
            int row = idx >> 4, seg = idx & 15;
            uint32_t off = (uint32_t)row * AROWB + seg * 16;
            size_t go = (size_t)row * 6144 + seg * 8;
            cp16(base + KHO + off, kH + go);
            cp16(base + VHO + off, vH + go);
        }
    };
    cp_commit();
    loadKV(0, 0); cp_commit();
    loadKV(1, 1); cp_commit();

    float o[16][4];
    #pragma unroll
    for (int i = 0; i < 16; i++)
        #pragma unroll
        for (int e = 0; e < 4; e++) o[i][e] = 0.f;
    float m0r = -1e30f, m1r = -1e30f, l0r = 0.f, l1r = 0.f;

    const float sscale = 0.08838834764831845f;   // 1/sqrt(128)

    const uint32_t qoff = (uint32_t)(wid * 16 + ((lane >> 3) & 1) * 8 + l7) * AROWB
                        + ((lane >> 4) & 1) * 16 + QH_OFF;
    const uint32_t koff = (uint32_t)(((lane >> 4) & 1) * 8 + l7) * AROWB
                        + ((lane >> 3) & 1) * 16;
    const uint32_t voff = (uint32_t)(((lane >> 3) & 1) * 8 + l7) * AROWB
                        + ((lane >> 4) & 1) * 16;

    const float* arow0 = alibi + ((size_t)h * S_ + (q0 + wid * 16 + g)) * S_;
    const float* arow1 = arow0 + 8 * S_;
    const float* padS  = (const float*)smem;

    cp_wait1();
    __syncthreads();
    uint32_t qf[8][4];
    #pragma unroll
    for (int kc2 = 0; kc2 < 8; kc2++)
        ldm4(qf[kc2][0], qf[kc2][1], qf[kc2][2], qf[kc2][3],
             sb + qoff + kc2 * 32);

    for (int kt = 0; kt < S_ / 64; kt++) {
        cp_wait1();
        __syncthreads();
        const uint32_t st = sb + KV_OFF + (uint32_t)(kt & 1) * ST_B;
        const int k0 = kt * 64;

        float c[8][4];
        #pragma unroll
        for (int i = 0; i < 8; i++)
            #pragma unroll
            for (int e = 0; e < 4; e++) c[i][e] = 0.f;

        uint32_t kf[2][4][4];
        #pragma unroll
        for (int np = 0; np < 4; np++)
            ldm4(kf[0][np][0], kf[0][np][1], kf[0][np][2], kf[0][np][3],
                 st + KHO + koff + (uint32_t)np * (16 * AROWB));

        #pragma unroll
        for (int kc2 = 0; kc2 < 8; kc2++) {
            const int cur = kc2 & 1, nxt = cur ^ 1;
            if (kc2 < 7) {
                #pragma unroll
                for (int np = 0; np < 4; np++)
                    ldm4(kf[nxt][np][0], kf[nxt][np][1],
                         kf[nxt][np][2], kf[nxt][np][3],
                         st + KHO + koff + (uint32_t)np * (16 * AROWB)
                            + (kc2 + 1) * 32);
            }
            #pragma unroll
            for (int np = 0; np < 4; np++) {
                mma16h(c[2 * np],     qf[kc2], &kf[cur][np][0]);
                mma16h(c[2 * np + 1], qf[kc2], &kf[cur][np][2]);
            }
        }

        #pragma unroll
        for (int nt = 0; nt < 8; nt++) {
            int col = k0 + nt * 8 + 2 * q;
            float2 a0 = *(const float2*)(arow0 + col);
            float2 a1 = *(const float2*)(arow1 + col);
            float2 pd = *(const float2*)(padS + col);
            c[nt][0] = fmaf(c[nt][0], sscale, a0.x + pd.x);
            c[nt][1] = fmaf(c[nt][1], sscale, a0.y + pd.y);
            c[nt][2] = fmaf(c[nt][2], sscale, a1.x + pd.x);
            c[nt][3] = fmaf(c[nt][3], sscale, a1.y + pd.y);
        }
        float mx0 = -1e30f, mx1 = -1e30f;
        #pragma unroll
        for (int nt = 0; nt < 8; nt++) {
            mx0 = fmaxf(mx0, fmaxf(c[nt][0], c[nt][1]));
            mx1 = fmaxf(mx1, fmaxf(c[nt][2], c[nt][3]));
        }
        mx0 = fmaxf(mx0, __shfl_xor_sync(0xffffffffu, mx0, 1));
        mx0 = fmaxf(mx0, __shfl_xor_sync(0xffffffffu, mx0, 2));
        mx1 = fmaxf(mx1, __shfl_xor_sync(0xffffffffu, mx1, 1));
        mx1 = fmaxf(mx1, __shfl_xor_sync(0xffffffffu, mx1, 2));
        float mn0 = fmaxf(m0r, mx0), mn1 = fmaxf(m1r, mx1);
        float cr0 = __expf(m0r - mn0), cr1 = __expf(m1r - mn1);
        m0r = mn0; m1r = mn1;
        float s0 = 0.f, s1 = 0.f;
        #pragma unroll
        for (int nt = 0; nt < 8; nt++) {
            c[nt][0] = __expf(c[nt][0] - mn0);
            c[nt][1] = __expf(c[nt][1] - mn0);
            c[nt][2] = __expf(c[nt][2] - mn1);
            c[nt][3] = __expf(c[nt][3] - mn1);
            s0 += c[nt][0] + c[nt][1];
            s1 += c[nt][2] + c[nt][3];
        }
        s0 += __shfl_xor_sync(0xffffffffu, s0, 1);
        s0 += __shfl_xor_sync(0xffffffffu, s0, 2);
        s1 += __shfl_xor_sync(0xffffffffu, s1, 1);
        s1 += __shfl_xor_sync(0xffffffffu, s1, 2);
        l0r = l0r * cr0 + s0;
        l1r = l1r * cr1 + s1;
        #pragma unroll
        for (int i = 0; i < 16; i++) {
            o[i][0] *= cr0; o[i][1] *= cr0;
            o[i][2] *= cr1; o[i][3] *= cr1;
        }

        #pragma unroll
        for (int kc2 = 0; kc2 < 4; kc2++) {
            uint32_t ph[4];
            ph[0] = packh_rn(c[2 * kc2][0],     c[2 * kc2][1]);
            ph[1] = packh_rn(c[2 * kc2][2],     c[2 * kc2][3]);
            ph[2] = packh_rn(c[2 * kc2 + 1][0], c[2 * kc2 + 1][1]);
            ph[3] = packh_rn(c[2 * kc2 + 1][2], c[2 * kc2 + 1][3]);
            uint32_t vrow = st + VHO + voff + (uint32_t)kc2 * (16 * AROWB);
            uint32_t vf[2][4];
            ldm4t(vf[0][0], vf[0][1], vf[0][2], vf[0][3], vrow);
            #pragma unroll
            for (int dg = 0; dg < 8; dg++) {
                const int cur = dg & 1, nxt = cur ^ 1;
                if (dg < 7)
                    ldm4t(vf[nxt][0], vf[nxt][1], vf[nxt][2], vf[nxt][3],
                          vrow + (dg + 1) * 32);
                mma16h(o[2 * dg],     ph, &vf[cur][0]);
                mma16h(o[2 * dg + 1], ph, &vf[cur][2]);
            }
        }

        __syncthreads();
        if (kt + 2 < S_ / 64) { loadKV(kt + 2, kt & 1); cp_commit(); }
        else cp_commit();
    }

    float inv0 = 1.0f / l0r, inv1 = 1.0f / l1r;
    size_t row0 = tokbase + q0 + wid * 16 + g;
    size_t row1 = row0 + 8;
    #pragma unroll
    for (int nt = 0; nt < 16; nt++) {
        int col = h * 128 + nt * 8 + 2 * q;
        *(uint32_t*)&outh[row0 * D_ + col] =
            packh_rn(o[nt][0] * inv0, o[nt][1] * inv0);
        *(uint32_t*)&outh[row1 * D_ + col] =
            packh_rn(o[nt][2] * inv1, o[nt][3] * inv1);
    }
}

// ---------------------------------------------------------------------------
// kernel_launch
// ---------------------------------------------------------------------------
extern "C" void kernel_launch(void* const* d_in, const int* in_sizes, int n_in,
                              void* d_out, int out_size)
{
    const float* x     = (const float*)d_in[0];
    const float* alibi = (const float*)d_in[1];
    const float* pad   = (const float*)d_in[2];
    const float* Wqkv  = (const float*)d_in[3];
    const float* Aqkv  = (const float*)d_in[4];
    const float* Bqkv  = (const float*)d_in[5];
    const float* Wout  = (const float*)d_in[6];
    const float* Aout  = (const float*)d_in[7];
    const float* Bout  = (const float*)d_in[8];
    float* out = (float*)d_out;

    __half *qkvh, *xh, *wqh, *woh, *ah;
    cudaGetSymbolAddress((void**)&qkvh, g_qkvh);
    cudaGetSymbolAddress((void**)&xh,  g_xh);
    cudaGetSymbolAddress((void**)&wqh, g_wqh);
    cudaGetSymbolAddress((void**)&woh, g_woh);
    cudaGetSymbolAddress((void**)&ah,  g_ah);

    cudaFuncSetAttribute(tc_gemm_fp16,
                         cudaFuncAttributeMaxDynamicSharedMemorySize, TCG_SMEM);
    cudaFuncSetAttribute(attn_mma,
                         cudaFuncAttributeMaxDynamicSharedMemorySize, ATTN_SMEM);

    // pre-pass: x -> fp16; weights -> fp16 with LoRA folded in fp32
    convh_kernel<<<(M_TOK * D_ / 4 + 255) / 256, 256>>>(
        (const float4*)x, (uint2*)xh, M_TOK * D_ / 4);
    {
        dim3 gq(D_ / 64, (3 * D_) / 64);
        weff_kernel<<<gq, 256>>>(Wqkv, Aqkv, Bqkv, wqh, 3 * D_, D_, LORA_SCALE);
        dim3 go(D_ / 64, D_ / 64);
        weff_kernel<<<go, 256>>>(Wout, Aout, Bout, woh, D_, D_, LORA_SCALE);
    }

    // qkv = x @ Weff_qkv^T  -> fp16 (1-pass)
    {
        dim3 grid((3 * D_) / 128, M_TOK / 128);
        tc_gemm_fp16<<<grid, 128, TCG_SMEM>>>(xh, wqh,
                                              nullptr, (uint16_t*)qkvh,
                                              M_TOK, 3 * D_, D_, 1);
    }

    // attention -> fp16 ah
    {
        dim3 grid(S_ / 64, H_, B_);
        attn_mma<<<grid, 128, ATTN_SMEM>>>(qkvh, alibi, pad, (uint16_t*)ah);
    }

    // out = attn @ Weff_out^T  -> fp32 (1-pass)
    {
        dim3 grid(D_ / 128, M_TOK / 128);
        tc_gemm_fp16<<<grid, 128, TCG_SMEM>>>(ah, woh,
                                              out, nullptr,
                                              M_TOK, D_, D_, 0);
    }
}

// round 16
// speedup vs baseline: 1.1782x; 1.0126x over previous
#include <cuda_runtime.h>
#include <cuda_fp16.h>
#include <cstdint>

// Problem constants
#define B_   2
#define S_   2048
#define D_   2048
#define H_   16
#define HD_  128
#define R_   32
#define M_TOK (B_ * S_)              // 4096 tokens
#define LORA_SCALE (1.0f / 32.0f)

// ---------------------------------------------------------------------------
// Scratch (allocation-free rule: __device__ globals)
// ---------------------------------------------------------------------------
static __device__ __align__(16) __half g_qkvh[M_TOK * 3 * D_];
static __device__ __align__(16) __half g_xh[M_TOK * D_];
static __device__ __align__(16) __half g_wqh[3 * D_ * D_];   // Wqkv + LoRA folded
static __device__ __align__(16) __half g_woh[D_ * D_];       // Wout + LoRA folded
static __device__ __align__(16) __half g_ah[M_TOK * D_];

// ---------------------------------------------------------------------------
// helpers
// ---------------------------------------------------------------------------
__device__ __forceinline__ uint32_t smem_u32(const void* p) {
    uint32_t a;
    asm("{ .reg .u64 t; cvta.to.shared.u64 t, %1; cvt.u32.u64 %0, t; }"
        : "=r"(a) : "l"(p));
    return a;
}
__device__ __forceinline__ void cp16(uint32_t dst, const void* src) {
    asm volatile("cp.async.cg.shared.global [%0], [%1], 16;"
                 :: "r"(dst), "l"(src) : "memory");
}
__device__ __forceinline__ void cp_commit() {
    asm volatile("cp.async.commit_group;" ::: "memory");
}
__device__ __forceinline__ void cp_wait1() {
    asm volatile("cp.async.wait_group 1;" ::: "memory");
}
__device__ __forceinline__ void cp_wait2() {
    asm volatile("cp.async.wait_group 2;" ::: "memory");
}
__device__ __forceinline__ void ldm4(uint32_t& r0, uint32_t& r1,
                                     uint32_t& r2, uint32_t& r3, uint32_t addr) {
    asm volatile("ldmatrix.sync.aligned.m8n8.x4.shared.b16 {%0,%1,%2,%3}, [%4];"
                 : "=r"(r0), "=r"(r1), "=r"(r2), "=r"(r3) : "r"(addr));
}
__device__ __forceinline__ void ldm4t(uint32_t& r0, uint32_t& r1,
                                      uint32_t& r2, uint32_t& r3, uint32_t addr) {
    asm volatile("ldmatrix.sync.aligned.m8n8.x4.trans.shared.b16 {%0,%1,%2,%3}, [%4];"
                 : "=r"(r0), "=r"(r1), "=r"(r2), "=r"(r3) : "r"(addr));
}
__device__ __forceinline__ void mma16h(float* c, const uint32_t* a, const uint32_t* b) {
    asm volatile(
        "mma.sync.aligned.m16n8k16.row.col.f32.f16.f16.f32 "
        "{%0,%1,%2,%3}, {%4,%5,%6,%7}, {%8,%9}, {%0,%1,%2,%3};"
        : "+f"(c[0]), "+f"(c[1]), "+f"(c[2]), "+f"(c[3])
        : "r"(a[0]), "r"(a[1]), "r"(a[2]), "r"(a[3]), "r"(b[0]), "r"(b[1]));
}
__device__ __forceinline__ uint32_t packh_rn(float x, float y) {
    __half2 t = __floats2half2_rn(x, y);
    return *(uint32_t*)&t;
}

// ---------------------------------------------------------------------------
// Pre-pass: fp32 -> fp16 RN (x only)
// ---------------------------------------------------------------------------
__global__ void __launch_bounds__(256) convh_kernel(
    const float4* __restrict__ src, uint2* __restrict__ dst, int n4)
{
    int i = blockIdx.x * 256 + threadIdx.x;
    if (i >= n4) return;
    float4 v = src[i];
    dst[i] = make_uint2(packh_rn(v.x, v.y), packh_rn(v.z, v.w));
}

// ---------------------------------------------------------------------------
// Pre-pass: fold LoRA into weight, fp32 -> fp16:
//   Weff[n][k] = W[n][k] + scale * sum_r A[k][r] * Bm[r][n]
// ---------------------------------------------------------------------------
__global__ void __launch_bounds__(256) weff_kernel(
    const float* __restrict__ W, const float* __restrict__ A,
    const float* __restrict__ Bm, __half* __restrict__ outW,
    int N, int K, float scale)
{
    __shared__ float As[64][33];   // [k][r]
    __shared__ float Bs[64][33];   // [n][r]

    const int tid = threadIdx.x;
    const int k0 = blockIdx.x * 64;
    const int n0 = blockIdx.y * 64;

    #pragma unroll
    for (int j = 0; j < 8; j++) {
        int idx = tid + j * 256;
        int kk = idx >> 5, r = idx & 31;
        As[kk][r] = A[(size_t)(k0 + kk) * 32 + r];
    }
    #pragma unroll
    for (int j = 0; j < 8; j++) {
        int idx = tid + j * 256;
        int r = idx >> 6, nn = idx & 63;
        Bs[nn][r] = Bm[(size_t)r * N + n0 + nn];
    }
    __syncthreads();

    const int tk = tid & 15;
    const int tn = tid >> 4;

    float acc[4][4];
    #pragma unroll
    for (int i = 0; i < 4; i++)
        #pragma unroll
        for (int j = 0; j < 4; j++) acc[i][j] = 0.f;

    #pragma unroll
    for (int r = 0; r < 32; r++) {
        float a[4], b[4];
        #pragma unroll
        for (int j = 0; j < 4; j++) a[j] = As[tk * 4 + j][r];
        #pragma unroll
        for (int i = 0; i < 4; i++) b[i] = Bs[tn * 4 + i][r];
        #pragma unroll
        for (int i = 0; i < 4; i++)
            #pragma unroll
            for (int j = 0; j < 4; j++)
                acc[i][j] = fmaf(b[i], a[j], acc[i][j]);
    }

    #pragma unroll
    for (int i = 0; i < 4; i++) {
        int n = n0 + tn * 4 + i;
        float4 w = *(const float4*)&W[(size_t)n * K + k0 + tk * 4];
        uint2 o;
        o.x = packh_rn(fmaf(scale, acc[i][0], w.x), fmaf(scale, acc[i][1], w.y));
        o.y = packh_rn(fmaf(scale, acc[i][2], w.z), fmaf(scale, acc[i][3], w.w));
        *(uint2*)&outW[(size_t)n * K + k0 + tk * 4] = o;
    }
}

// ---------------------------------------------------------------------------
// fp16 GEMM v3 (1-pass, LoRA pre-folded into B):  C = Ah @ Bh^T
// CTA tile 128x128, 4 warps in 2x2, warp tile 64x64 -> occ 2.
// (unchanged from round 15 — passing, 56% tensor)
// ---------------------------------------------------------------------------
#define GROW 80
#define OFF_B  (128 * GROW)               // 10240
#define STAGE_B (2 * 128 * GROW)          // 20480
#define TCG_SMEM (4 * STAGE_B)            // 81920 bytes

__global__ void __launch_bounds__(128, 2) tc_gemm_fp16(
    const __half* __restrict__ Ah, const __half* __restrict__ Bh,
    float* __restrict__ Cf, uint16_t* __restrict__ Chi,
    int M, int N, int K, int outMode)
{
    extern __shared__ __align__(128) char smem[];
    const uint32_t sbase = smem_u32(smem);

    const int tid  = threadIdx.x;
    const int wid  = tid >> 5;
    const int lane = tid & 31;
    const int g    = lane >> 2;
    const int q    = lane & 3;
    const int warpM = (wid & 1) * 64;
    const int warpN = (wid >> 1) * 64;

    const int n0 = blockIdx.x * 128;
    const int m0 = blockIdx.y * 128;

    const int kc = K >> 5;

    float acc[4][8][4];
    #pragma unroll
    for (int i = 0; i < 4; i++)
        #pragma unroll
        for (int j = 0; j < 8; j++)
            #pragma unroll
            for (int e = 0; e < 4; e++) acc[i][j][e] = 0.f;

    auto issue = [&](int c, int s) {
        const uint32_t st = sbase + (uint32_t)s * STAGE_B;
        #pragma unroll
        for (int j = 0; j < 4; j++) {
            int idx = tid + j * 128;
            int row = idx >> 2;
            int seg = idx & 3;
            uint32_t doff = (uint32_t)row * GROW + (uint32_t)seg * 16u;
            cp16(st + doff,         Ah + (size_t)(m0 + row) * K + c * 32 + seg * 8);
            cp16(st + OFF_B + doff, Bh + (size_t)(n0 + row) * K + c * 32 + seg * 8);
        }
        cp_commit();
    };

    issue(0, 0);
    issue(1, 1);
    issue(2, 2);

    const int mi = lane >> 3;
    const int l7 = lane & 7;

    for (int i = 0; i < kc; i++) {
        cp_wait2();
        __syncthreads();
        if (i + 3 < kc) issue(i + 3, (i + 3) & 3);
        else cp_commit();

        const uint32_t st = sbase + (uint32_t)(i & 3) * STAGE_B;

        #pragma unroll
        for (int kh = 0; kh < 2; kh++) {
            uint32_t bh[8][2];
            #pragma unroll
            for (int bg = 0; bg < 4; bg++) {
                uint32_t rowB = warpN + bg * 16 + ((mi >> 1) << 3) + l7;
                uint32_t addr = st + OFF_B + rowB * GROW
                              + (uint32_t)(mi & 1) * 16u + kh * 32u;
                ldm4(bh[2 * bg][0], bh[2 * bg][1],
                     bh[2 * bg + 1][0], bh[2 * bg + 1][1], addr);
            }
            #pragma unroll
            for (int mt = 0; mt < 4; mt++) {
                uint32_t rowA = warpM + mt * 16 + ((mi & 1) << 3) + l7;
                uint32_t addrA = st + rowA * GROW
                               + (uint32_t)(mi >> 1) * 16u + kh * 32u;
                uint32_t ah[4];
                ldm4(ah[0], ah[1], ah[2], ah[3], addrA);
                #pragma unroll
                for (int nt = 0; nt < 8; nt++)
                    mma16h(acc[mt][nt], ah, bh[nt]);
            }
        }
    }

    #pragma unroll
    for (int mt = 0; mt < 4; mt++) {
        int row = m0 + warpM + mt * 16 + g;
        #pragma unroll
        for (int nt = 0; nt < 8; nt++) {
            int col = n0 + warpN + nt * 8 + 2 * q;
            size_t i0 = (size_t)row * N + col;
            size_t i1 = (size_t)(row + 8) * N + col;
            if (outMode == 0) {
                *(float2*)&Cf[i0] = make_float2(acc[mt][nt][0], acc[mt][nt][1]);
                *(float2*)&Cf[i1] = make_float2(acc[mt][nt][2], acc[mt][nt][3]);
            } else {
                *(uint32_t*)&Chi[i0] = packh_rn(acc[mt][nt][0], acc[mt][nt][1]);
                *(uint32_t*)&Chi[i1] = packh_rn(acc[mt][nt][2], acc[mt][nt][3]);
            }
        }
    }
}

// ---------------------------------------------------------------------------
// Tensor-core flash attention, fp16 1-pass, occupancy-2:
// ALIBI/PAD PREFETCH: bias operands loaded into registers at ktile-loop top,
// before the QK mma block, hiding ~600cyc DRAM latency under the mma.
// Arithmetic unchanged -> bit-identical results.
// ---------------------------------------------------------------------------
#define AROWB 272
#define PAD_OFF 0
#define PAD_B   (S_ * 4)                       // 8192
#define QH_OFF  PAD_B
#define KV_OFF  (QH_OFF + 64 * AROWB)
#define KHO 0
#define VHO (64 * AROWB)
#define ST_B (2 * 64 * AROWB)
#define ATTN_SMEM (KV_OFF + 2 * ST_B)          // 95232

__global__ void __launch_bounds__(128, 2) attn_mma(
    const __half* __restrict__ qkvh,
    const float* __restrict__ alibi, const float* __restrict__ pad,
    uint16_t* __restrict__ outh)
{
    extern __shared__ __align__(128) char smem[];
    const uint32_t sb = smem_u32(smem);
    const int tid = threadIdx.x, wid = tid >> 5, lane = tid & 31;
    const int g = lane >> 2, q = lane & 3, l7 = lane & 7;
    const int q0 = blockIdx.x * 64, h = blockIdx.y, b = blockIdx.z;

    const size_t tokbase = (size_t)(b * S_);

    {
        const float* prow = pad + (size_t)b * S_;
        #pragma unroll
        for (int j = 0; j < 4; j++) {
            int idx = tid + j * 128;
            cp16(sb + PAD_OFF + idx * 16, prow + idx * 4);
        }
        const __half* bH = qkvh + (tokbase + q0) * 6144 + h * 128;
        #pragma unroll
        for (int j = 0; j < 8; j++) {
            int idx = tid + j * 128;
            int row = idx >> 4, seg = idx & 15;
            cp16(sb + QH_OFF + (uint32_t)row * AROWB + seg * 16,
                 bH + (size_t)row * 6144 + seg * 8);
        }
    }
    auto loadKV = [&](int kt, int st) {
        const uint32_t base = sb + KV_OFF + (uint32_t)st * ST_B;
        const __half* kH = qkvh + (tokbase + kt * 64) * 6144 + D_ + h * 128;
        const __half* vH = kH + D_;
        #pragma unroll
        for (int j = 0; j < 8; j++) {
            int idx = tid + j * 128;
            int row = idx >> 4, seg = idx & 15;
            uint32_t off = (uint32_t)row * AROWB + seg * 16;
            size_t go = (size_t)row * 6144 + seg * 8;
            cp16(base + KHO + off, kH + go);
            cp16(base + VHO + off, vH + go);
        }
    };
    cp_commit();
    loadKV(0, 0); cp_commit();
    loadKV(1, 1); cp_commit();

    float o[16][4];
    #pragma unroll
    for (int i = 0; i < 16; i++)
        #pragma unroll
        for (int e = 0; e < 4; e++) o[i][e] = 0.f;
    float m0r = -1e30f, m1r = -1e30f, l0r = 0.f, l1r = 0.f;

    const float sscale = 0.08838834764831845f;   // 1/sqrt(128)

    const uint32_t qoff = (uint32_t)(wid * 16 + ((lane >> 3) & 1) * 8 + l7) * AROWB
                        + ((lane >> 4) & 1) * 16 + QH_OFF;
    const uint32_t koff = (uint32_t)(((lane >> 4) & 1) * 8 + l7) * AROWB
                        + ((lane >> 3) & 1) * 16;
    const uint32_t voff = (uint32_t)(((lane >> 3) & 1) * 8 + l7) * AROWB
                        + ((lane >> 4) & 1) * 16;

    const float* arow0 = alibi + ((size_t)h * S_ + (q0 + wid * 16 + g)) * S_;
    const float* arow1 = arow0 + 8 * S_;
    const float* padS  = (const float*)smem;

    cp_wait1();
    __syncthreads();
    uint32_t qf[8][4];
    #pragma unroll
    for (int kc2 = 0; kc2 < 8; kc2++)
        ldm4(qf[kc2][0], qf[kc2][1], qf[kc2][2], qf[kc2][3],
             sb + qoff + kc2 * 32);

    for (int kt = 0; kt < S_ / 64; kt++) {
        const int k0 = kt * 64;

        // ---- PREFETCH bias operands (registers; consumed after QK mma) ----
        float2 pa0[8], pa1[8], ppd[8];
        #pragma unroll
        for (int nt = 0; nt < 8; nt++) {
            int col = k0 + nt * 8 + 2 * q;
            pa0[nt] = *(const float2*)(arow0 + col);
            pa1[nt] = *(const float2*)(arow1 + col);
            ppd[nt] = *(const float2*)(padS + col);
        }

        cp_wait1();
        __syncthreads();
        const uint32_t st = sb + KV_OFF + (uint32_t)(kt & 1) * ST_B;

        // ---- QK^T (fp16, 1-pass; K double-buffered) ----
        float c[8][4];
        #pragma unroll
        for (int i = 0; i < 8; i++)
            #pragma unroll
            for (int e = 0; e < 4; e++) c[i][e] = 0.f;

        uint32_t kf[2][4][4];
        #pragma unroll
        for (int np = 0; np < 4; np++)
            ldm4(kf[0][np][0], kf[0][np][1], kf[0][np][2], kf[0][np][3],
                 st + KHO + koff + (uint32_t)np * (16 * AROWB));

        #pragma unroll
        for (int kc2 = 0; kc2 < 8; kc2++) {
            const int cur = kc2 & 1, nxt = cur ^ 1;
            if (kc2 < 7) {
                #pragma unroll
                for (int np = 0; np < 4; np++)
                    ldm4(kf[nxt][np][0], kf[nxt][np][1],
                         kf[nxt][np][2], kf[nxt][np][3],
                         st + KHO + koff + (uint32_t)np * (16 * AROWB)
                            + (kc2 + 1) * 32);
            }
            #pragma unroll
            for (int np = 0; np < 4; np++) {
                mma16h(c[2 * np],     qf[kc2], &kf[cur][np][0]);
                mma16h(c[2 * np + 1], qf[kc2], &kf[cur][np][2]);
            }
        }

        // ---- bias + online softmax (operands already in registers) ----
        #pragma unroll
        for (int nt = 0; nt < 8; nt++) {
            c[nt][0] = fmaf(c[nt][0], sscale, pa0[nt].x + ppd[nt].x);
            c[nt][1] = fmaf(c[nt][1], sscale, pa0[nt].y + ppd[nt].y);
            c[nt][2] = fmaf(c[nt][2], sscale, pa1[nt].x + ppd[nt].x);
            c[nt][3] = fmaf(c[nt][3], sscale, pa1[nt].y + ppd[nt].y);
        }
        float mx0 = -1e30f, mx1 = -1e30f;
        #pragma unroll
        for (int nt = 0; nt < 8; nt++) {
            mx0 = fmaxf(mx0, fmaxf(c[nt][0], c[nt][1]));
            mx1 = fmaxf(mx1, fmaxf(c[nt][2], c[nt][3]));
        }
        mx0 = fmaxf(mx0, __shfl_xor_sync(0xffffffffu, mx0, 1));
        mx0 = fmaxf(mx0, __shfl_xor_sync(0xffffffffu, mx0, 2));
        mx1 = fmaxf(mx1, __shfl_xor_sync(0xffffffffu, mx1, 1));
        mx1 = fmaxf(mx1, __shfl_xor_sync(0xffffffffu, mx1, 2));
        float mn0 = fmaxf(m0r, mx0), mn1 = fmaxf(m1r, mx1);
        float cr0 = __expf(m0r - mn0), cr1 = __expf(m1r - mn1);
        m0r = mn0; m1r = mn1;
        float s0 = 0.f, s1 = 0.f;
        #pragma unroll
        for (int nt = 0; nt < 8; nt++) {
            c[nt][0] = __expf(c[nt][0] - mn0);
            c[nt][1] = __expf(c[nt][1] - mn0);
            c[nt][2] = __expf(c[nt][2] - mn1);
            c[nt][3] = __expf(c[nt][3] - mn1);
            s0 += c[nt][0] + c[nt][1];
            s1 += c[nt][2] + c[nt][3];
        }
        s0 += __shfl_xor_sync(0xffffffffu, s0, 1);
        s0 += __shfl_xor_sync(0xffffffffu, s0, 2);
        s1 += __shfl_xor_sync(0xffffffffu, s1, 1);
        s1 += __shfl_xor_sync(0xffffffffu, s1, 2);
        l0r = l0r * cr0 + s0;
        l1r = l1r * cr1 + s1;
        #pragma unroll
        for (int i = 0; i < 16; i++) {
            o[i][0] *= cr0; o[i][1] *= cr0;
            o[i][2] *= cr1; o[i][3] *= cr1;
        }

        // ---- PV (fp16, 1-pass; V double-buffered) ----
        #pragma unroll
        for (int kc2 = 0; kc2 < 4; kc2++) {
            uint32_t ph[4];
            ph[0] = packh_rn(c[2 * kc2][0],     c[2 * kc2][1]);
            ph[1] = packh_rn(c[2 * kc2][2],     c[2 * kc2][3]);
            ph[2] = packh_rn(c[2 * kc2 + 1][0], c[2 * kc2 + 1][1]);
            ph[3] = packh_rn(c[2 * kc2 + 1][2], c[2 * kc2 + 1][3]);
            uint32_t vrow = st + VHO + voff + (uint32_t)kc2 * (16 * AROWB);
            uint32_t vf[2][4];
            ldm4t(vf[0][0], vf[0][1], vf[0][2], vf[0][3], vrow);
            #pragma unroll
            for (int dg = 0; dg < 8; dg++) {
                const int cur = dg & 1, nxt = cur ^ 1;
                if (dg < 7)
                    ldm4t(vf[nxt][0], vf[nxt][1], vf[nxt][2], vf[nxt][3],
                          vrow + (dg + 1) * 32);
                mma16h(o[2 * dg],     ph, &vf[cur][0]);
                mma16h(o[2 * dg + 1], ph, &vf[cur][2]);
            }
        }

        __syncthreads();
        if (kt + 2 < S_ / 64) { loadKV(kt + 2, kt & 1); cp_commit(); }
        else cp_commit();
    }

    float inv0 = 1.0f / l0r, inv1 = 1.0f / l1r;
    size_t row0 = tokbase + q0 + wid * 16 + g;
    size_t row1 = row0 + 8;
    #pragma unroll
    for (int nt = 0; nt < 16; nt++) {
        int col = h * 128 + nt * 8 + 2 * q;
        *(uint32_t*)&outh[row0 * D_ + col] =
            packh_rn(o[nt][0] * inv0, o[nt][1] * inv0);
        *(uint32_t*)&outh[row1 * D_ + col] =
            packh_rn(o[nt][2] * inv1, o[nt][3] * inv1);
    }
}

// ---------------------------------------------------------------------------
// kernel_launch
// ---------------------------------------------------------------------------
extern "C" void kernel_launch(void* const* d_in, const int* in_sizes, int n_in,
                              void* d_out, int out_size)
{
    const float* x     = (const float*)d_in[0];
    const float* alibi = (const float*)d_in[1];
    const float* pad   = (const float*)d_in[2];
    const float* Wqkv  = (const float*)d_in[3];
    const float* Aqkv  = (const float*)d_in[4];
    const float* Bqkv  = (const float*)d_in[5];
    const float* Wout  = (const float*)d_in[6];
    const float* Aout  = (const float*)d_in[7];
    const float* Bout  = (const float*)d_in[8];
    float* out = (float*)d_out;

    __half *qkvh, *xh, *wqh, *woh, *ah;
    cudaGetSymbolAddress((void**)&qkvh, g_qkvh);
    cudaGetSymbolAddress((void**)&xh,  g_xh);
    cudaGetSymbolAddress((void**)&wqh, g_wqh);
    cudaGetSymbolAddress((void**)&woh, g_woh);
    cudaGetSymbolAddress((void**)&ah,  g_ah);

    cudaFuncSetAttribute(tc_gemm_fp16,
                         cudaFuncAttributeMaxDynamicSharedMemorySize, TCG_SMEM);
    cudaFuncSetAttribute(attn_mma,
                         cudaFuncAttributeMaxDynamicSharedMemorySize, ATTN_SMEM);

    // pre-pass: x -> fp16; weights -> fp16 with LoRA folded in fp32
    convh_kernel<<<(M_TOK * D_ / 4 + 255) / 256, 256>>>(
        (const float4*)x, (uint2*)xh, M_TOK * D_ / 4);
    {
        dim3 gq(D_ / 64, (3 * D_) / 64);
        weff_kernel<<<gq, 256>>>(Wqkv, Aqkv, Bqkv, wqh, 3 * D_, D_, LORA_SCALE);
        dim3 go(D_ / 64, D_ / 64);
        weff_kernel<<<go, 256>>>(Wout, Aout, Bout, woh, D_, D_, LORA_SCALE);
    }

    // qkv = x @ Weff_qkv^T  -> fp16 (1-pass)
    {
        dim3 grid((3 * D_) / 128, M_TOK / 128);
        tc_gemm_fp16<<<grid, 128, TCG_SMEM>>>(xh, wqh,
                                              nullptr, (uint16_t*)qkvh,
                                              M_TOK, 3 * D_, D_, 1);
    }

    // attention -> fp16 ah
    {
        dim3 grid(S_ / 64, H_, B_);
        attn_mma<<<grid, 128, ATTN_SMEM>>>(qkvh, alibi, pad, (uint16_t*)ah);
    }

    // out = attn @ Weff_out^T  -> fp32 (1-pass)
    {
        dim3 grid(D_ / 128, M_TOK / 128);
        tc_gemm_fp16<<<grid, 128, TCG_SMEM>>>(ah, woh,
                                              out, nullptr,
                                              M_TOK, D_, D_, 0);
    }
}

// round 17
// speedup vs baseline: 1.2148x; 1.0311x over previous
#include <cuda_runtime.h>
#include <cuda_fp16.h>
#include <cstdint>

// Problem constants
#define B_   2
#define S_   2048
#define D_   2048
#define H_   16
#define HD_  128
#define R_   32
#define M_TOK (B_ * S_)              // 4096 tokens
#define LORA_SCALE (1.0f / 32.0f)

// ---------------------------------------------------------------------------
// Scratch (allocation-free rule: __device__ globals)
// ---------------------------------------------------------------------------
static __device__ __align__(16) __half g_qkvh[M_TOK * 3 * D_];
static __device__ __align__(16) __half g_xh[M_TOK * D_];
static __device__ __align__(16) __half g_wqh[3 * D_ * D_];   // Wqkv + LoRA folded
static __device__ __align__(16) __half g_woh[D_ * D_];       // Wout + LoRA folded
static __device__ __align__(16) __half g_ah[M_TOK * D_];

// ---------------------------------------------------------------------------
// helpers
// ---------------------------------------------------------------------------
__device__ __forceinline__ uint32_t smem_u32(const void* p) {
    uint32_t a;
    asm("{ .reg .u64 t; cvta.to.shared.u64 t, %1; cvt.u32.u64 %0, t; }"
        : "=r"(a) : "l"(p));
    return a;
}
__device__ __forceinline__ void cp16(uint32_t dst, const void* src) {
    asm volatile("cp.async.cg.shared.global [%0], [%1], 16;"
                 :: "r"(dst), "l"(src) : "memory");
}
__device__ __forceinline__ void cp_commit() {
    asm volatile("cp.async.commit_group;" ::: "memory");
}
__device__ __forceinline__ void cp_wait1() {
    asm volatile("cp.async.wait_group 1;" ::: "memory");
}
__device__ __forceinline__ void cp_wait2() {
    asm volatile("cp.async.wait_group 2;" ::: "memory");
}
__device__ __forceinline__ void ldm4(uint32_t& r0, uint32_t& r1,
                                     uint32_t& r2, uint32_t& r3, uint32_t addr) {
    asm volatile("ldmatrix.sync.aligned.m8n8.x4.shared.b16 {%0,%1,%2,%3}, [%4];"
                 : "=r"(r0), "=r"(r1), "=r"(r2), "=r"(r3) : "r"(addr));
}
__device__ __forceinline__ void ldm4t(uint32_t& r0, uint32_t& r1,
                                      uint32_t& r2, uint32_t& r3, uint32_t addr) {
    asm volatile("ldmatrix.sync.aligned.m8n8.x4.trans.shared.b16 {%0,%1,%2,%3}, [%4];"
                 : "=r"(r0), "=r"(r1), "=r"(r2), "=r"(r3) : "r"(addr));
}
__device__ __forceinline__ void mma16h(float* c, const uint32_t* a, const uint32_t* b) {
    asm volatile(
        "mma.sync.aligned.m16n8k16.row.col.f32.f16.f16.f32 "
        "{%0,%1,%2,%3}, {%4,%5,%6,%7}, {%8,%9}, {%0,%1,%2,%3};"
        : "+f"(c[0]), "+f"(c[1]), "+f"(c[2]), "+f"(c[3])
        : "r"(a[0]), "r"(a[1]), "r"(a[2]), "r"(a[3]), "r"(b[0]), "r"(b[1]));
}
__device__ __forceinline__ uint32_t packh_rn(float x, float y) {
    __half2 t = __floats2half2_rn(x, y);
    return *(uint32_t*)&t;
}
__device__ __forceinline__ uint32_t ex2_f16x2(uint32_t x) {
    uint32_t r;
    asm("ex2.approx.f16x2 %0, %1;" : "=r"(r) : "r"(x));
    return r;
}

// ---------------------------------------------------------------------------
// Pre-pass: fp32 -> fp16 RN (x only)
// ---------------------------------------------------------------------------
__global__ void __launch_bounds__(256) convh_kernel(
    const float4* __restrict__ src, uint2* __restrict__ dst, int n4)
{
    int i = blockIdx.x * 256 + threadIdx.x;
    if (i >= n4) return;
    float4 v = src[i];
    dst[i] = make_uint2(packh_rn(v.x, v.y), packh_rn(v.z, v.w));
}

// ---------------------------------------------------------------------------
// Pre-pass: fold LoRA into weight, fp32 -> fp16:
//   Weff[n][k] = W[n][k] + scale * sum_r A[k][r] * Bm[r][n]
// ---------------------------------------------------------------------------
__global__ void __launch_bounds__(256) weff_kernel(
    const float* __restrict__ W, const float* __restrict__ A,
    const float* __restrict__ Bm, __half* __restrict__ outW,
    int N, int K, float scale)
{
    __shared__ float As[64][33];   // [k][r]
    __shared__ float Bs[64][33];   // [n][r]

    const int tid = threadIdx.x;
    const int k0 = blockIdx.x * 64;
    const int n0 = blockIdx.y * 64;

    #pragma unroll
    for (int j = 0; j < 8; j++) {
        int idx = tid + j * 256;
        int kk = idx >> 5, r = idx & 31;
        As[kk][r] = A[(size_t)(k0 + kk) * 32 + r];
    }
    #pragma unroll
    for (int j = 0; j < 8; j++) {
        int idx = tid + j * 256;
        int r = idx >> 6, nn = idx & 63;
        Bs[nn][r] = Bm[(size_t)r * N + n0 + nn];
    }
    __syncthreads();

    const int tk = tid & 15;
    const int tn = tid >> 4;

    float acc[4][4];
    #pragma unroll
    for (int i = 0; i < 4; i++)
        #pragma unroll
        for (int j = 0; j < 4; j++) acc[i][j] = 0.f;

    #pragma unroll
    for (int r = 0; r < 32; r++) {
        float a[4], b[4];
        #pragma unroll
        for (int j = 0; j < 4; j++) a[j] = As[tk * 4 + j][r];
        #pragma unroll
        for (int i = 0; i < 4; i++) b[i] = Bs[tn * 4 + i][r];
        #pragma unroll
        for (int i = 0; i < 4; i++)
            #pragma unroll
            for (int j = 0; j < 4; j++)
                acc[i][j] = fmaf(b[i], a[j], acc[i][j]);
    }

    #pragma unroll
    for (int i = 0; i < 4; i++) {
        int n = n0 + tn * 4 + i;
        float4 w = *(const float4*)&W[(size_t)n * K + k0 + tk * 4];
        uint2 o;
        o.x = packh_rn(fmaf(scale, acc[i][0], w.x), fmaf(scale, acc[i][1], w.y));
        o.y = packh_rn(fmaf(scale, acc[i][2], w.z), fmaf(scale, acc[i][3], w.w));
        *(uint2*)&outW[(size_t)n * K + k0 + tk * 4] = o;
    }
}

// ---------------------------------------------------------------------------
// fp16 GEMM v3 (1-pass, LoRA pre-folded into B):  C = Ah @ Bh^T
// CTA tile 128x128, 4 warps in 2x2, warp tile 64x64 -> occ 2.
// (unchanged from round 15/16 — passing)
// ---------------------------------------------------------------------------
#define GROW 80
#define OFF_B  (128 * GROW)               // 10240
#define STAGE_B (2 * 128 * GROW)          // 20480
#define TCG_SMEM (4 * STAGE_B)            // 81920 bytes

__global__ void __launch_bounds__(128, 2) tc_gemm_fp16(
    const __half* __restrict__ Ah, const __half* __restrict__ Bh,
    float* __restrict__ Cf, uint16_t* __restrict__ Chi,
    int M, int N, int K, int outMode)
{
    extern __shared__ __align__(128) char smem[];
    const uint32_t sbase = smem_u32(smem);

    const int tid  = threadIdx.x;
    const int wid  = tid >> 5;
    const int lane = tid & 31;
    const int g    = lane >> 2;
    const int q    = lane & 3;
    const int warpM = (wid & 1) * 64;
    const int warpN = (wid >> 1) * 64;

    const int n0 = blockIdx.x * 128;
    const int m0 = blockIdx.y * 128;

    const int kc = K >> 5;

    float acc[4][8][4];
    #pragma unroll
    for (int i = 0; i < 4; i++)
        #pragma unroll
        for (int j = 0; j < 8; j++)
            #pragma unroll
            for (int e = 0; e < 4; e++) acc[i][j][e] = 0.f;

    auto issue = [&](int c, int s) {
        const uint32_t st = sbase + (uint32_t)s * STAGE_B;
        #pragma unroll
        for (int j = 0; j < 4; j++) {
            int idx = tid + j * 128;
            int row = idx >> 2;
            int seg = idx & 3;
            uint32_t doff = (uint32_t)row * GROW + (uint32_t)seg * 16u;
            cp16(st + doff,         Ah + (size_t)(m0 + row) * K + c * 32 + seg * 8);
            cp16(st + OFF_B + doff, Bh + (size_t)(n0 + row) * K + c * 32 + seg * 8);
        }
        cp_commit();
    };

    issue(0, 0);
    issue(1, 1);
    issue(2, 2);

    const int mi = lane >> 3;
    const int l7 = lane & 7;

    for (int i = 0; i < kc; i++) {
        cp_wait2();
        __syncthreads();
        if (i + 3 < kc) issue(i + 3, (i + 3) & 3);
        else cp_commit();

        const uint32_t st = sbase + (uint32_t)(i & 3) * STAGE_B;

        #pragma unroll
        for (int kh = 0; kh < 2; kh++) {
            uint32_t bh[8][2];
            #pragma unroll
            for (int bg = 0; bg < 4; bg++) {
                uint32_t rowB = warpN + bg * 16 + ((mi >> 1) << 3) + l7;
                uint32_t addr = st + OFF_B + rowB * GROW
                              + (uint32_t)(mi & 1) * 16u + kh * 32u;
                ldm4(bh[2 * bg][0], bh[2 * bg][1],
                     bh[2 * bg + 1][0], bh[2 * bg + 1][1], addr);
            }
            #pragma unroll
            for (int mt = 0; mt < 4; mt++) {
                uint32_t rowA = warpM + mt * 16 + ((mi & 1) << 3) + l7;
                uint32_t addrA = st + rowA * GROW
                               + (uint32_t)(mi >> 1) * 16u + kh * 32u;
                uint32_t ah[4];
                ldm4(ah[0], ah[1], ah[2], ah[3], addrA);
                #pragma unroll
                for (int nt = 0; nt < 8; nt++)
                    mma16h(acc[mt][nt], ah, bh[nt]);
            }
        }
    }

    #pragma unroll
    for (int mt = 0; mt < 4; mt++) {
        int row = m0 + warpM + mt * 16 + g;
        #pragma unroll
        for (int nt = 0; nt < 8; nt++) {
            int col = n0 + warpN + nt * 8 + 2 * q;
            size_t i0 = (size_t)row * N + col;
            size_t i1 = (size_t)(row + 8) * N + col;
            if (outMode == 0) {
                *(float2*)&Cf[i0] = make_float2(acc[mt][nt][0], acc[mt][nt][1]);
                *(float2*)&Cf[i1] = make_float2(acc[mt][nt][2], acc[mt][nt][3]);
            } else {
                *(uint32_t*)&Chi[i0] = packh_rn(acc[mt][nt][0], acc[mt][nt][1]);
                *(uint32_t*)&Chi[i1] = packh_rn(acc[mt][nt][2], acc[mt][nt][3]);
            }
        }
    }
}

// ---------------------------------------------------------------------------
// Tensor-core flash attention, fp16 1-pass, occupancy-2:
// Softmax exp via ex2.approx.f16x2 (2 values/MUFU op); exp outputs ARE the
// fp16 P fragments (no separate pack in PV). l sums the rounded P values
// (consistent normalizer -> error cancellation in num/denom).
// ---------------------------------------------------------------------------
#define AROWB 272
#define PAD_OFF 0
#define PAD_B   (S_ * 4)                       // 8192
#define QH_OFF  PAD_B
#define KV_OFF  (QH_OFF + 64 * AROWB)
#define KHO 0
#define VHO (64 * AROWB)
#define ST_B (2 * 64 * AROWB)
#define ATTN_SMEM (KV_OFF + 2 * ST_B)          // 95232

__global__ void __launch_bounds__(128, 2) attn_mma(
    const __half* __restrict__ qkvh,
    const float* __restrict__ alibi, const float* __restrict__ pad,
    uint16_t* __restrict__ outh)
{
    extern __shared__ __align__(128) char smem[];
    const uint32_t sb = smem_u32(smem);
    const int tid = threadIdx.x, wid = tid >> 5, lane = tid & 31;
    const int g = lane >> 2, q = lane & 3, l7 = lane & 7;
    const int q0 = blockIdx.x * 64, h = blockIdx.y, b = blockIdx.z;

    const size_t tokbase = (size_t)(b * S_);

    {
        const float* prow = pad + (size_t)b * S_;
        #pragma unroll
        for (int j = 0; j < 4; j++) {
            int idx = tid + j * 128;
            cp16(sb + PAD_OFF + idx * 16, prow + idx * 4);
        }
        const __half* bH = qkvh + (tokbase + q0) * 6144 + h * 128;
        #pragma unroll
        for (int j = 0; j < 8; j++) {
            int idx = tid + j * 128;
            int row = idx >> 4, seg = idx & 15;
            cp16(sb + QH_OFF + (uint32_t)row * AROWB + seg * 16,
                 bH + (size_t)row * 6144 + seg * 8);
        }
    }
    auto loadKV = [&](int kt, int st) {
        const uint32_t base = sb + KV_OFF + (uint32_t)st * ST_B;
        const __half* kH = qkvh + (tokbase + kt * 64) * 6144 + D_ + h * 128;
        const __half* vH = kH + D_;
        #pragma unroll
        for (int j = 0; j < 8; j++) {
            int idx = tid + j * 128;
            int row = idx >> 4, seg = idx & 15;
            uint32_t off = (uint32_t)row * AROWB + seg * 16;
            size_t go = (size_t)row * 6144 + seg * 8;
            cp16(base + KHO + off, kH + go);
            cp16(base + VHO + off, vH + go);
        }
    };
    cp_commit();
    loadKV(0, 0); cp_commit();
    loadKV(1, 1); cp_commit();

    float o[16][4];
    #pragma unroll
    for (int i = 0; i < 16; i++)
        #pragma unroll
        for (int e = 0; e < 4; e++) o[i][e] = 0.f;
    float m0r = -1e30f, m1r = -1e30f, l0r = 0.f, l1r = 0.f;

    const float sscale = 0.08838834764831845f;   // 1/sqrt(128)
    const float LOG2E  = 1.4426950408889634f;

    const uint32_t qoff = (uint32_t)(wid * 16 + ((lane >> 3) & 1) * 8 + l7) * AROWB
                        + ((lane >> 4) & 1) * 16 + QH_OFF;
    const uint32_t koff = (uint32_t)(((lane >> 4) & 1) * 8 + l7) * AROWB
                        + ((lane >> 3) & 1) * 16;
    const uint32_t voff = (uint32_t)(((lane >> 3) & 1) * 8 + l7) * AROWB
                        + ((lane >> 4) & 1) * 16;

    const float* arow0 = alibi + ((size_t)h * S_ + (q0 + wid * 16 + g)) * S_;
    const float* arow1 = arow0 + 8 * S_;
    const float* padS  = (const float*)smem;

    cp_wait1();
    __syncthreads();
    uint32_t qf[8][4];
    #pragma unroll
    for (int kc2 = 0; kc2 < 8; kc2++)
        ldm4(qf[kc2][0], qf[kc2][1], qf[kc2][2], qf[kc2][3],
             sb + qoff + kc2 * 32);

    for (int kt = 0; kt < S_ / 64; kt++) {
        const int k0 = kt * 64;

        // ---- PREFETCH bias operands ----
        float2 pa0[8], pa1[8], ppd[8];
        #pragma unroll
        for (int nt = 0; nt < 8; nt++) {
            int col = k0 + nt * 8 + 2 * q;
            pa0[nt] = *(const float2*)(arow0 + col);
            pa1[nt] = *(const float2*)(arow1 + col);
            ppd[nt] = *(const float2*)(padS + col);
        }

        cp_wait1();
        __syncthreads();
        const uint32_t st = sb + KV_OFF + (uint32_t)(kt & 1) * ST_B;

        // ---- QK^T (fp16, 1-pass; K double-buffered) ----
        float c[8][4];
        #pragma unroll
        for (int i = 0; i < 8; i++)
            #pragma unroll
            for (int e = 0; e < 4; e++) c[i][e] = 0.f;

        uint32_t kf[2][4][4];
        #pragma unroll
        for (int np = 0; np < 4; np++)
            ldm4(kf[0][np][0], kf[0][np][1], kf[0][np][2], kf[0][np][3],
                 st + KHO + koff + (uint32_t)np * (16 * AROWB));

        #pragma unroll
        for (int kc2 = 0; kc2 < 8; kc2++) {
            const int cur = kc2 & 1, nxt = cur ^ 1;
            if (kc2 < 7) {
                #pragma unroll
                for (int np = 0; np < 4; np++)
                    ldm4(kf[nxt][np][0], kf[nxt][np][1],
                         kf[nxt][np][2], kf[nxt][np][3],
                         st + KHO + koff + (uint32_t)np * (16 * AROWB)
                            + (kc2 + 1) * 32);
            }
            #pragma unroll
            for (int np = 0; np < 4; np++) {
                mma16h(c[2 * np],     qf[kc2], &kf[cur][np][0]);
                mma16h(c[2 * np + 1], qf[kc2], &kf[cur][np][2]);
            }
        }

        // ---- bias ----
        #pragma unroll
        for (int nt = 0; nt < 8; nt++) {
            c[nt][0] = fmaf(c[nt][0], sscale, pa0[nt].x + ppd[nt].x);
            c[nt][1] = fmaf(c[nt][1], sscale, pa0[nt].y + ppd[nt].y);
            c[nt][2] = fmaf(c[nt][2], sscale, pa1[nt].x + ppd[nt].x);
            c[nt][3] = fmaf(c[nt][3], sscale, pa1[nt].y + ppd[nt].y);
        }
        // ---- online softmax (exp in fp16x2) ----
        float mx0 = -1e30f, mx1 = -1e30f;
        #pragma unroll
        for (int nt = 0; nt < 8; nt++) {
            mx0 = fmaxf(mx0, fmaxf(c[nt][0], c[nt][1]));
            mx1 = fmaxf(mx1, fmaxf(c[nt][2], c[nt][3]));
        }
        mx0 = fmaxf(mx0, __shfl_xor_sync(0xffffffffu, mx0, 1));
        mx0 = fmaxf(mx0, __shfl_xor_sync(0xffffffffu, mx0, 2));
        mx1 = fmaxf(mx1, __shfl_xor_sync(0xffffffffu, mx1, 1));
        mx1 = fmaxf(mx1, __shfl_xor_sync(0xffffffffu, mx1, 2));
        float mn0 = fmaxf(m0r, mx0), mn1 = fmaxf(m1r, mx1);
        float cr0 = __expf(m0r - mn0), cr1 = __expf(m1r - mn1);
        m0r = mn0; m1r = mn1;
        const float mnl0 = mn0 * LOG2E, mnl1 = mn1 * LOG2E;

        uint32_t ph[4][4];      // P fragments, fp16x2, kept for PV
        float s0 = 0.f, s1 = 0.f;
        #pragma unroll
        for (int nt = 0; nt < 8; nt++) {
            float t0 = fmaf(c[nt][0], LOG2E, -mnl0);
            float t1 = fmaf(c[nt][1], LOG2E, -mnl0);
            float t2 = fmaf(c[nt][2], LOG2E, -mnl1);
            float t3 = fmaf(c[nt][3], LOG2E, -mnl1);
            uint32_t e01 = ex2_f16x2(packh_rn(t0, t1));
            uint32_t e23 = ex2_f16x2(packh_rn(t2, t3));
            ph[nt >> 1][(nt & 1) * 2 + 0] = e01;
            ph[nt >> 1][(nt & 1) * 2 + 1] = e23;
            float2 f01 = __half22float2(*(__half2*)&e01);
            float2 f23 = __half22float2(*(__half2*)&e23);
            s0 += f01.x + f01.y;
            s1 += f23.x + f23.y;
        }
        s0 += __shfl_xor_sync(0xffffffffu, s0, 1);
        s0 += __shfl_xor_sync(0xffffffffu, s0, 2);
        s1 += __shfl_xor_sync(0xffffffffu, s1, 1);
        s1 += __shfl_xor_sync(0xffffffffu, s1, 2);
        l0r = l0r * cr0 + s0;
        l1r = l1r * cr1 + s1;
        #pragma unroll
        for (int i = 0; i < 16; i++) {
            o[i][0] *= cr0; o[i][1] *= cr0;
            o[i][2] *= cr1; o[i][3] *= cr1;
        }

        // ---- PV (fp16, 1-pass; V double-buffered; P fragments ready) ----
        #pragma unroll
        for (int kc2 = 0; kc2 < 4; kc2++) {
            uint32_t vrow = st + VHO + voff + (uint32_t)kc2 * (16 * AROWB);
            uint32_t vf[2][4];
            ldm4t(vf[0][0], vf[0][1], vf[0][2], vf[0][3], vrow);
            #pragma unroll
            for (int dg = 0; dg < 8; dg++) {
                const int cur = dg & 1, nxt = cur ^ 1;
                if (dg < 7)
                    ldm4t(vf[nxt][0], vf[nxt][1], vf[nxt][2], vf[nxt][3],
                          vrow + (dg + 1) * 32);
                mma16h(o[2 * dg],     ph[kc2], &vf[cur][0]);
                mma16h(o[2 * dg + 1], ph[kc2], &vf[cur][2]);
            }
        }

        __syncthreads();
        if (kt + 2 < S_ / 64) { loadKV(kt + 2, kt & 1); cp_commit(); }
        else cp_commit();
    }

    float inv0 = 1.0f / l0r, inv1 = 1.0f / l1r;
    size_t row0 = tokbase + q0 + wid * 16 + g;
    size_t row1 = row0 + 8;
    #pragma unroll
    for (int nt = 0; nt < 16; nt++) {
        int col = h * 128 + nt * 8 + 2 * q;
        *(uint32_t*)&outh[row0 * D_ + col] =
            packh_rn(o[nt][0] * inv0, o[nt][1] * inv0);
        *(uint32_t*)&outh[row1 * D_ + col] =
            packh_rn(o[nt][2] * inv1, o[nt][3] * inv1);
    }
}

// ---------------------------------------------------------------------------
// kernel_launch
// ---------------------------------------------------------------------------
extern "C" void kernel_launch(void* const* d_in, const int* in_sizes, int n_in,
                              void* d_out, int out_size)
{
    const float* x     = (const float*)d_in[0];
    const float* alibi = (const float*)d_in[1];
    const float* pad   = (const float*)d_in[2];
    const float* Wqkv  = (const float*)d_in[3];
    const float* Aqkv  = (const float*)d_in[4];
    const float* Bqkv  = (const float*)d_in[5];
    const float* Wout  = (const float*)d_in[6];
    const float* Aout  = (const float*)d_in[7];
    const float* Bout  = (const float*)d_in[8];
    float* out = (float*)d_out;

    __half *qkvh, *xh, *wqh, *woh, *ah;
    cudaGetSymbolAddress((void**)&qkvh, g_qkvh);
    cudaGetSymbolAddress((void**)&xh,  g_xh);
    cudaGetSymbolAddress((void**)&wqh, g_wqh);
    cudaGetSymbolAddress((void**)&woh, g_woh);
    cudaGetSymbolAddress((void**)&ah,  g_ah);

    cudaFuncSetAttribute(tc_gemm_fp16,
                         cudaFuncAttributeMaxDynamicSharedMemorySize, TCG_SMEM);
    cudaFuncSetAttribute(attn_mma,
                         cudaFuncAttributeMaxDynamicSharedMemorySize, ATTN_SMEM);

    // pre-pass: x -> fp16; weights -> fp16 with LoRA folded in fp32
    convh_kernel<<<(M_TOK * D_ / 4 + 255) / 256, 256>>>(
        (const float4*)x, (uint2*)xh, M_TOK * D_ / 4);
    {
        dim3 gq(D_ / 64, (3 * D_) / 64);
        weff_kernel<<<gq, 256>>>(Wqkv, Aqkv, Bqkv, wqh, 3 * D_, D_, LORA_SCALE);
        dim3 go(D_ / 64, D_ / 64);
        weff_kernel<<<go, 256>>>(Wout, Aout, Bout, woh, D_, D_, LORA_SCALE);
    }

    // qkv = x @ Weff_qkv^T  -> fp16 (1-pass)
    {
        dim3 grid((3 * D_) / 128, M_TOK / 128);
        tc_gemm_fp16<<<grid, 128, TCG_SMEM>>>(xh, wqh,
                                              nullptr, (uint16_t*)qkvh,
                                              M_TOK, 3 * D_, D_, 1);
    }

    // attention -> fp16 ah
    {
        dim3 grid(S_ / 64, H_, B_);
        attn_mma<<<grid, 128, ATTN_SMEM>>>(qkvh, alibi, pad, (uint16_t*)ah);
    }

    // out = attn @ Weff_out^T  -> fp32 (1-pass)
    {
        dim3 grid(D_ / 128, M_TOK / 128);
        tc_gemm_fp16<<<grid, 128, TCG_SMEM>>>(ah, woh,
                                              out, nullptr,
                                              M_TOK, D_, D_, 0);
    }
}